// round 14
// baseline (speedup 1.0000x reference)
#include <cuda_runtime.h>
#include <cuda_fp16.h>
#include <cstdint>
#include <math.h>

#define BATCH 4
#define SEQ   2048
#define DIM   512
#define HEADS 8
#define DHEAD 64
#define QKVC  1536
#define MTOT  (BATCH * SEQ)   // 8192

// ---------------------------------------------------------------------------
// Scratch (__device__ globals)
// ---------------------------------------------------------------------------
__device__ __align__(16) __half g_xh [(size_t)MTOT * DIM];
__device__ __align__(16) __half g_wh [(size_t)QKVC * DIM];
__device__ __align__(16) __half g_uh [(size_t)DIM * DIM];
__device__ __align__(16) __half g_qkv[(size_t)MTOT * QKVC];
__device__ __align__(16) __half g_ah [(size_t)MTOT * DIM];

// ---------------------------------------------------------------------------
// Helpers
// ---------------------------------------------------------------------------
__device__ __forceinline__ uint32_t smem_u32(const void* p) {
    uint32_t a;
    asm("{ .reg .u64 t; cvta.to.shared.u64 t, %1; cvt.u32.u64 %0, t; }"
        : "=r"(a) : "l"(p));
    return a;
}

__device__ __forceinline__ float ex2(float x) {
    float y;
    asm("ex2.approx.f32 %0, %1;" : "=f"(y) : "f"(x));
    return y;
}

__device__ __forceinline__ void ldmatrix_x4(
    uint32_t& r0, uint32_t& r1, uint32_t& r2, uint32_t& r3, uint32_t addr)
{
    asm volatile("ldmatrix.sync.aligned.m8n8.x4.shared.b16 {%0,%1,%2,%3}, [%4];"
                 : "=r"(r0), "=r"(r1), "=r"(r2), "=r"(r3) : "r"(addr));
}

__device__ __forceinline__ void ldmatrix_x4_trans(
    uint32_t& r0, uint32_t& r1, uint32_t& r2, uint32_t& r3, uint32_t addr)
{
    asm volatile("ldmatrix.sync.aligned.m8n8.x4.trans.shared.b16 {%0,%1,%2,%3}, [%4];"
                 : "=r"(r0), "=r"(r1), "=r"(r2), "=r"(r3) : "r"(addr));
}

__device__ __forceinline__ void mma_f16(
    float* d, uint32_t a0, uint32_t a1, uint32_t a2, uint32_t a3,
    uint32_t b0, uint32_t b1)
{
    asm volatile(
        "mma.sync.aligned.m16n8k16.row.col.f32.f16.f16.f32 "
        "{%0,%1,%2,%3}, {%4,%5,%6,%7}, {%8,%9}, {%0,%1,%2,%3};"
        : "+f"(d[0]), "+f"(d[1]), "+f"(d[2]), "+f"(d[3])
        : "r"(a0), "r"(a1), "r"(a2), "r"(a3), "r"(b0), "r"(b1));
}

__device__ __forceinline__ void cp_async16(uint32_t dst, const void* src) {
    asm volatile("cp.async.cg.shared.global [%0], [%1], 16;" :: "r"(dst), "l"(src));
}

__device__ __forceinline__ uint32_t pack_f16(float p0, float p1) {
    __half2 hh = __floats2half2_rn(p0, p1);
    return *reinterpret_cast<uint32_t*>(&hh);
}

// ---------------------------------------------------------------------------
// Fused fp32 -> fp16 conversion (one launch)
// ---------------------------------------------------------------------------
#define N4_X  (MTOT * DIM / 4)
#define N4_W  (QKVC * DIM / 4)
#define N4_U  (DIM * DIM / 4)
#define N4_TOT (N4_X + N4_W + N4_U)

__global__ __launch_bounds__(256) void conv_all(
    const float4* __restrict__ x, __half* __restrict__ xh,
    const float4* __restrict__ w, __half* __restrict__ wh,
    const float4* __restrict__ u, __half* __restrict__ uh)
{
    int i = blockIdx.x * 256 + threadIdx.x;
    if (i >= N4_TOT) return;
    const float4* src;
    __half* dst;
    int j;
    if (i < N4_X)            { src = x; dst = xh; j = i; }
    else if (i < N4_X + N4_W){ src = w; dst = wh; j = i - N4_X; }
    else                     { src = u; dst = uh; j = i - N4_X - N4_W; }
    float4 v = src[j];
    __half2 h0 = __floats2half2_rn(v.x, v.y);
    __half2 h1 = __floats2half2_rn(v.z, v.w);
    uint2 o;
    o.x = *reinterpret_cast<uint32_t*>(&h0);
    o.y = *reinterpret_cast<uint32_t*>(&h1);
    *(uint2*)(dst + 4 * (size_t)j) = o;
}

// ---------------------------------------------------------------------------
// 1-term fp16 GEMM, BK=64, 3-stage cp.async pipeline (unchanged from R13).
// ---------------------------------------------------------------------------
#define GLD     72
#define GTILE_E (128 * GLD)
#define GSTAGES 3
#define GEMM_SMEM (GSTAGES * 2 * GTILE_E * 2) // 110592 B

template <bool F32OUT>
__global__ __launch_bounds__(256, 2) void gemm_f16_1t(
    const __half* __restrict__ Ah, const __half* __restrict__ Bh,
    __half* __restrict__ Ch, float* __restrict__ Cf, int M, int N, int K)
{
    extern __shared__ __half smh16[];
    const uint32_t sbase = smem_u32(smh16);

    const int tid  = threadIdx.x;
    const int wid  = tid >> 5;
    const int lane = tid & 31;
    const int warp_m = wid >> 2;
    const int warp_n = wid & 3;
    const int m0 = blockIdx.y * 128;
    const int n0 = blockIdx.x * 128;

    const __half* srcs[2] = { Ah + (size_t)m0 * K, Bh + (size_t)n0 * K };

    const int lr   = lane & 15;
    const int kofs = (lane & 16) ? 8 : 0;

    float acc[4][4][4];
#pragma unroll
    for (int mi = 0; mi < 4; mi++)
#pragma unroll
        for (int ni = 0; ni < 4; ni++)
#pragma unroll
            for (int r = 0; r < 4; r++) acc[mi][ni][r] = 0.f;

    const int nchunks = K / 64;

    auto issue_stage = [&](int st, int k0) {
#pragma unroll
        for (int t = 0; t < 2; t++) {
#pragma unroll
            for (int q = 0; q < 4; q++) {
                int v   = tid + q * 256;
                int row = v >> 3;
                int seg = v & 7;
                uint32_t dst = sbase +
                    (uint32_t)(((st * 2 + t) * GTILE_E + row * GLD + seg * 8) * 2);
                cp_async16(dst, srcs[t] + (size_t)row * K + k0 + seg * 8);
            }
        }
        asm volatile("cp.async.commit_group;");
    };

    issue_stage(0, 0);
    issue_stage(1, 64);

    for (int c = 0; c < nchunks; c++) {
        if (c + 2 < nchunks) {
            issue_stage((c + 2) % GSTAGES, (c + 2) * 64);
            asm volatile("cp.async.wait_group 2;");
        } else if (c + 1 < nchunks) {
            asm volatile("cp.async.wait_group 1;");
        } else {
            asm volatile("cp.async.wait_group 0;");
        }
        __syncthreads();

        const uint32_t stb = sbase + (uint32_t)(((c % GSTAGES) * 2) * GTILE_E * 2);

#pragma unroll
        for (int ks = 0; ks < 64; ks += 16) {
            uint32_t Af[4][4];
#pragma unroll
            for (int mi = 0; mi < 4; mi++) {
                int row = warp_m * 64 + mi * 16 + lr;
                uint32_t a0 = stb + (uint32_t)((0 * GTILE_E + row * GLD + ks + kofs) * 2);
                ldmatrix_x4(Af[mi][0], Af[mi][1], Af[mi][2], Af[mi][3], a0);
            }
            uint32_t Bf[4][2];
#pragma unroll
            for (int bi = 0; bi < 2; bi++) {
                int row = warp_n * 32 + bi * 16 + lr;
                uint32_t b0 = stb + (uint32_t)((1 * GTILE_E + row * GLD + ks + kofs) * 2);
                uint32_t r0, r1, r2, r3;
                ldmatrix_x4(r0, r1, r2, r3, b0);
                Bf[bi * 2][0] = r0; Bf[bi * 2][1] = r2;
                Bf[bi * 2 + 1][0] = r1; Bf[bi * 2 + 1][1] = r3;
            }
#pragma unroll
            for (int mi = 0; mi < 4; mi++)
#pragma unroll
                for (int ni = 0; ni < 4; ni++)
                    mma_f16(acc[mi][ni], Af[mi][0], Af[mi][1], Af[mi][2], Af[mi][3],
                            Bf[ni][0], Bf[ni][1]);
        }
        __syncthreads();
    }

    const int g = lane >> 2, tig = lane & 3;
#pragma unroll
    for (int mi = 0; mi < 4; mi++) {
#pragma unroll
        for (int ni = 0; ni < 4; ni++) {
            int row = m0 + warp_m * 64 + mi * 16 + g;
            int col = n0 + warp_n * 32 + ni * 8 + tig * 2;
            float* d = acc[mi][ni];
            if (F32OUT) {
                *(float2*)&Cf[(size_t)row * N + col] = make_float2(d[0], d[1]);
                *(float2*)&Cf[(size_t)(row + 8) * N + col] = make_float2(d[2], d[3]);
            } else {
                __half2 h0 = __floats2half2_rn(d[0], d[1]);
                __half2 h1 = __floats2half2_rn(d[2], d[3]);
                *(uint32_t*)&Ch[(size_t)row * N + col] = *(uint32_t*)&h0;
                *(uint32_t*)&Ch[(size_t)(row + 8) * N + col] = *(uint32_t*)&h1;
            }
        }
    }
}

// ---------------------------------------------------------------------------
// Flash attention: 1-term S, 1-term PV, static softmax.
// 2-stage pipeline, 128 keys per stage processed as two 64-key halves
// (identical accumulation order as before -> bitwise-identical numerics).
// ---------------------------------------------------------------------------
#define FLD 72
#define FKEYS 128                               // keys per stage
#define FSTAGE_E (2 * FKEYS * FLD)              // K tile + V tile
#define FLASH_SMEM ((128 * FLD + 2 * FSTAGE_E) * 2)   // 92160 B

__global__ __launch_bounds__(256, 2) void flash_mma(
    const __half* __restrict__ qkv, __half* __restrict__ oh)
{
    extern __shared__ __half smh[];
    __half* Qh = smh;
    __half* KV = smh + 128 * FLD;

    const int tid  = threadIdx.x;
    const int wid  = tid >> 5;
    const int lane = tid & 31;
    const int g    = lane >> 2;
    const int tq   = lane & 3;
    const int lr   = lane & 15;
    const int kofs = (lane & 16) ? 8 : 0;

    const int b  = blockIdx.y >> 3;
    const int h  = blockIdx.y & 7;
    const int q0 = blockIdx.x * 128;
    const size_t qrowg = (size_t)(b * SEQ + q0);

    // Q load (joins first commit group)
    {
#pragma unroll
        for (int q = 0; q < 4; q++) {
            int v = tid + q * 256;
            int row = v >> 3, seg = v & 7;
            cp_async16(smem_u32(Qh + row * FLD + seg * 8),
                       qkv + (qrowg + row) * QKVC + h * DHEAD + seg * 8);
        }
    }
    // one stage = K[128 keys x 64] + V[128 keys x 64]
    auto issue_kv = [&](int st, int ktile) {
        const size_t krow = (size_t)(b * SEQ + ktile * FKEYS);
        __half* dst0 = KV + st * FSTAGE_E;
#pragma unroll
        for (int t = 0; t < 2; t++) {
            const int colb = 512 + t * 512 + h * DHEAD;
#pragma unroll
            for (int q = 0; q < 4; q++) {
                int v = tid + q * 256;          // 0..1023 -> 128 rows x 8 segs
                int row = v >> 3, seg = v & 7;
                cp_async16(smem_u32(dst0 + t * FKEYS * FLD + row * FLD + seg * 8),
                           qkv + (krow + row) * QKVC + colb + seg * 8);
            }
        }
        asm volatile("cp.async.commit_group;");
    };
    issue_kv(0, 0);   // group 0 = Q + KV0

    float l_i[2] = {0.f, 0.f};
    float O[8][4];
#pragma unroll
    for (int j = 0; j < 8; j++)
#pragma unroll
        for (int r = 0; r < 4; r++) O[j][r] = 0.f;

    uint32_t qhf[4][4];

    const float CSC = 0.125f * 1.4426950408889634f;
    const int mi_pv = lane >> 3, ri_pv = lane & 7;
    const int keyb  = ((mi_pv & 1) << 3) + ri_pv;
    const int dimb  = (mi_pv >> 1) << 3;
    const int NIT = SEQ / FKEYS;    // 16

    for (int c = 0; c < NIT; c++) {
        if (c + 1 < NIT) {
            issue_kv((c + 1) & 1, c + 1);
            asm volatile("cp.async.wait_group 1;");
        } else {
            asm volatile("cp.async.wait_group 0;");
        }
        __syncthreads();

        if (c == 0) {
#pragma unroll
            for (int kk = 0; kk < 4; kk++)
                ldmatrix_x4(qhf[kk][0], qhf[kk][1], qhf[kk][2], qhf[kk][3],
                    smem_u32(Qh + (wid * 16 + lr) * FLD + kk * 16 + kofs));
        }

        const __half* Kbase = KV + (c & 1) * FSTAGE_E;
        const __half* Vbase = Kbase + FKEYS * FLD;

#pragma unroll
        for (int half = 0; half < 2; half++) {
            const __half* Kh = Kbase + half * 64 * FLD;
            const __half* Vh = Vbase + half * 64 * FLD;

            // ---- S = Qhi @ Khi^T ----
            float S[8][4];
#pragma unroll
            for (int j = 0; j < 8; j++)
#pragma unroll
                for (int r = 0; r < 4; r++) S[j][r] = 0.f;

#pragma unroll
            for (int kk = 0; kk < 4; kk++) {
#pragma unroll
                for (int bi = 0; bi < 4; bi++) {
                    uint32_t kh0, kh1, kh2, kh3;
                    ldmatrix_x4(kh0, kh1, kh2, kh3,
                        smem_u32(Kh + (bi * 16 + lr) * FLD + kk * 16 + kofs));
                    mma_f16(S[bi * 2],     qhf[kk][0], qhf[kk][1], qhf[kk][2], qhf[kk][3], kh0, kh2);
                    mma_f16(S[bi * 2 + 1], qhf[kk][0], qhf[kk][1], qhf[kk][2], qhf[kk][3], kh1, kh3);
                }
            }

            // ---- P = exp2(S * CSC); accumulate l per-lane ----
#pragma unroll
            for (int j = 0; j < 8; j++) {
                float p0 = ex2(S[j][0] * CSC);
                float p1 = ex2(S[j][1] * CSC);
                float p2 = ex2(S[j][2] * CSC);
                float p3 = ex2(S[j][3] * CSC);
                S[j][0] = p0; S[j][1] = p1; S[j][2] = p2; S[j][3] = p3;
                l_i[0] += p0 + p1;
                l_i[1] += p2 + p3;
            }

            // ---- O += Phi @ Vhi ----
#pragma unroll
            for (int kk = 0; kk < 4; kk++) {
                uint32_t ph[4];
                ph[0] = pack_f16(S[2 * kk][0],     S[2 * kk][1]);
                ph[1] = pack_f16(S[2 * kk][2],     S[2 * kk][3]);
                ph[2] = pack_f16(S[2 * kk + 1][0], S[2 * kk + 1][1]);
                ph[3] = pack_f16(S[2 * kk + 1][2], S[2 * kk + 1][3]);

                const int key = kk * 16 + keyb;
#pragma unroll
                for (int jj = 0; jj < 4; jj++) {
                    uint32_t t0, t1, t2, t3;
                    ldmatrix_x4_trans(t0, t1, t2, t3,
                        smem_u32(Vh + key * FLD + jj * 16 + dimb));
                    mma_f16(O[jj * 2],     ph[0], ph[1], ph[2], ph[3], t0, t1);
                    mma_f16(O[jj * 2 + 1], ph[0], ph[1], ph[2], ph[3], t2, t3);
                }
            }
        }
        __syncthreads();
    }

    l_i[0] += __shfl_xor_sync(0xffffffffu, l_i[0], 1);
    l_i[0] += __shfl_xor_sync(0xffffffffu, l_i[0], 2);
    l_i[1] += __shfl_xor_sync(0xffffffffu, l_i[1], 1);
    l_i[1] += __shfl_xor_sync(0xffffffffu, l_i[1], 2);
    const float inv0 = 1.f / l_i[0];
    const float inv1 = 1.f / l_i[1];
    const size_t row0 = qrowg + wid * 16 + g;
#pragma unroll
    for (int j = 0; j < 8; j++) {
        const int col = h * DHEAD + j * 8 + tq * 2;
        *(uint32_t*)&oh[row0 * DIM + col] =
            pack_f16(O[j][0] * inv0, O[j][1] * inv0);
        *(uint32_t*)&oh[(row0 + 8) * DIM + col] =
            pack_f16(O[j][2] * inv1, O[j][3] * inv1);
    }
}

// ---------------------------------------------------------------------------
extern "C" void kernel_launch(void* const* d_in, const int* in_sizes, int n_in,
                              void* d_out, int out_size)
{
    const float* x    = (const float*)d_in[0];
    const float* Wqkv = (const float*)d_in[1];
    const float* Wout = (const float*)d_in[2];
    float* out = (float*)d_out;

    __half *xh, *wh, *uh, *qkv, *ah;
    cudaGetSymbolAddress((void**)&xh,  g_xh);
    cudaGetSymbolAddress((void**)&wh,  g_wh);
    cudaGetSymbolAddress((void**)&uh,  g_uh);
    cudaGetSymbolAddress((void**)&qkv, g_qkv);
    cudaGetSymbolAddress((void**)&ah,  g_ah);

    cudaFuncSetAttribute(gemm_f16_1t<false>,
                         cudaFuncAttributeMaxDynamicSharedMemorySize, GEMM_SMEM);
    cudaFuncSetAttribute(gemm_f16_1t<true>,
                         cudaFuncAttributeMaxDynamicSharedMemorySize, GEMM_SMEM);
    cudaFuncSetAttribute(flash_mma,
                         cudaFuncAttributeMaxDynamicSharedMemorySize, FLASH_SMEM);

    // 0) all fp32 -> fp16 conversions in one launch
    conv_all<<<(N4_TOT + 255) / 256, 256>>>(
        (const float4*)x, xh, (const float4*)Wqkv, wh, (const float4*)Wout, uh);

    // 1) QKV projection (1-term fp16, BK=64, 3-stage) -> fp16 qkv
    gemm_f16_1t<false><<<dim3(QKVC / 128, MTOT / 128), 256, GEMM_SMEM>>>(
        xh, wh, qkv, nullptr, MTOT, QKVC, DIM);

    // 2) flash attention (1-term S/PV, static softmax, 128-key stages) -> fp16
    flash_mma<<<dim3(SEQ / 128, BATCH * HEADS), 256, FLASH_SMEM>>>(qkv, ah);

    // 3) out projection (1-term fp16, BK=64, 3-stage) -> fp32
    gemm_f16_1t<true><<<dim3(DIM / 128, MTOT / 128), 256, GEMM_SMEM>>>(
        ah, uh, nullptr, out, MTOT, DIM, DIM);
}

// round 15
// speedup vs baseline: 1.0716x; 1.0716x over previous
#include <cuda_runtime.h>
#include <cuda_fp16.h>
#include <cstdint>
#include <math.h>

#define BATCH 4
#define SEQ   2048
#define DIM   512
#define HEADS 8
#define DHEAD 64
#define QKVC  1536
#define MTOT  (BATCH * SEQ)   // 8192

// ---------------------------------------------------------------------------
// Scratch (__device__ globals)
// ---------------------------------------------------------------------------
__device__ __align__(16) __half g_xh [(size_t)MTOT * DIM];
__device__ __align__(16) __half g_wh [(size_t)QKVC * DIM];
__device__ __align__(16) __half g_uh [(size_t)DIM * DIM];
__device__ __align__(16) __half g_qkv[(size_t)MTOT * QKVC];
__device__ __align__(16) __half g_ah [(size_t)MTOT * DIM];

// ---------------------------------------------------------------------------
// Helpers
// ---------------------------------------------------------------------------
__device__ __forceinline__ uint32_t smem_u32(const void* p) {
    uint32_t a;
    asm("{ .reg .u64 t; cvta.to.shared.u64 t, %1; cvt.u32.u64 %0, t; }"
        : "=r"(a) : "l"(p));
    return a;
}

__device__ __forceinline__ float ex2(float x) {
    float y;
    asm("ex2.approx.f32 %0, %1;" : "=f"(y) : "f"(x));
    return y;
}

__device__ __forceinline__ void ldmatrix_x4(
    uint32_t& r0, uint32_t& r1, uint32_t& r2, uint32_t& r3, uint32_t addr)
{
    asm volatile("ldmatrix.sync.aligned.m8n8.x4.shared.b16 {%0,%1,%2,%3}, [%4];"
                 : "=r"(r0), "=r"(r1), "=r"(r2), "=r"(r3) : "r"(addr));
}

__device__ __forceinline__ void ldmatrix_x4_trans(
    uint32_t& r0, uint32_t& r1, uint32_t& r2, uint32_t& r3, uint32_t addr)
{
    asm volatile("ldmatrix.sync.aligned.m8n8.x4.trans.shared.b16 {%0,%1,%2,%3}, [%4];"
                 : "=r"(r0), "=r"(r1), "=r"(r2), "=r"(r3) : "r"(addr));
}

__device__ __forceinline__ void mma_f16(
    float* d, uint32_t a0, uint32_t a1, uint32_t a2, uint32_t a3,
    uint32_t b0, uint32_t b1)
{
    asm volatile(
        "mma.sync.aligned.m16n8k16.row.col.f32.f16.f16.f32 "
        "{%0,%1,%2,%3}, {%4,%5,%6,%7}, {%8,%9}, {%0,%1,%2,%3};"
        : "+f"(d[0]), "+f"(d[1]), "+f"(d[2]), "+f"(d[3])
        : "r"(a0), "r"(a1), "r"(a2), "r"(a3), "r"(b0), "r"(b1));
}

__device__ __forceinline__ void cp_async16(uint32_t dst, const void* src) {
    asm volatile("cp.async.cg.shared.global [%0], [%1], 16;" :: "r"(dst), "l"(src));
}

__device__ __forceinline__ uint32_t pack_f16(float p0, float p1) {
    __half2 hh = __floats2half2_rn(p0, p1);
    return *reinterpret_cast<uint32_t*>(&hh);
}

// ---------------------------------------------------------------------------
// Fused fp32 -> fp16 conversion (one launch)
// ---------------------------------------------------------------------------
#define N4_X  (MTOT * DIM / 4)
#define N4_W  (QKVC * DIM / 4)
#define N4_U  (DIM * DIM / 4)
#define N4_TOT (N4_X + N4_W + N4_U)

__global__ __launch_bounds__(256) void conv_all(
    const float4* __restrict__ x, __half* __restrict__ xh,
    const float4* __restrict__ w, __half* __restrict__ wh,
    const float4* __restrict__ u, __half* __restrict__ uh)
{
    int i = blockIdx.x * 256 + threadIdx.x;
    if (i >= N4_TOT) return;
    const float4* src;
    __half* dst;
    int j;
    if (i < N4_X)            { src = x; dst = xh; j = i; }
    else if (i < N4_X + N4_W){ src = w; dst = wh; j = i - N4_X; }
    else                     { src = u; dst = uh; j = i - N4_X - N4_W; }
    float4 v = src[j];
    __half2 h0 = __floats2half2_rn(v.x, v.y);
    __half2 h1 = __floats2half2_rn(v.z, v.w);
    uint2 o;
    o.x = *reinterpret_cast<uint32_t*>(&h0);
    o.y = *reinterpret_cast<uint32_t*>(&h1);
    *(uint2*)(dst + 4 * (size_t)j) = o;
}

// ---------------------------------------------------------------------------
// 1-term fp16 GEMM, BK=64, STAGES-deep cp.async pipeline.
// C = Ah[M,K] @ Bh[N,K]^T, fp32 accum. F32OUT selects output type.
// ---------------------------------------------------------------------------
#define GLD     72
#define GTILE_E (128 * GLD)
#define GEMM_SMEM(S) ((S) * 2 * GTILE_E * 2)

template <bool F32OUT, int STAGES>
__global__ __launch_bounds__(256, 2) void gemm_f16_1t(
    const __half* __restrict__ Ah, const __half* __restrict__ Bh,
    __half* __restrict__ Ch, float* __restrict__ Cf, int M, int N, int K)
{
    extern __shared__ __half smh16[];
    const uint32_t sbase = smem_u32(smh16);

    const int tid  = threadIdx.x;
    const int wid  = tid >> 5;
    const int lane = tid & 31;
    const int warp_m = wid >> 2;
    const int warp_n = wid & 3;
    const int m0 = blockIdx.y * 128;
    const int n0 = blockIdx.x * 128;

    const __half* srcs[2] = { Ah + (size_t)m0 * K, Bh + (size_t)n0 * K };

    const int lr   = lane & 15;
    const int kofs = (lane & 16) ? 8 : 0;

    float acc[4][4][4];
#pragma unroll
    for (int mi = 0; mi < 4; mi++)
#pragma unroll
        for (int ni = 0; ni < 4; ni++)
#pragma unroll
            for (int r = 0; r < 4; r++) acc[mi][ni][r] = 0.f;

    const int nchunks = K / 64;

    auto issue_stage = [&](int st, int k0) {
#pragma unroll
        for (int t = 0; t < 2; t++) {
#pragma unroll
            for (int q = 0; q < 4; q++) {
                int v   = tid + q * 256;
                int row = v >> 3;
                int seg = v & 7;
                uint32_t dst = sbase +
                    (uint32_t)(((st * 2 + t) * GTILE_E + row * GLD + seg * 8) * 2);
                cp_async16(dst, srcs[t] + (size_t)row * K + k0 + seg * 8);
            }
        }
        asm volatile("cp.async.commit_group;");
    };

    // prologue: fill STAGES-1 stages
#pragma unroll
    for (int s = 0; s < STAGES - 1; s++)
        issue_stage(s, s * 64);

    for (int c = 0; c < nchunks; c++) {
        if (c + STAGES - 1 < nchunks) {
            issue_stage((c + STAGES - 1) % STAGES, (c + STAGES - 1) * 64);
            asm volatile("cp.async.wait_group %0;" :: "n"(STAGES - 1));
        } else if (c + 1 < nchunks) {
            // remaining in-flight groups: nchunks-1-c
            if (nchunks - 1 - c >= 2)
                asm volatile("cp.async.wait_group 2;");
            else
                asm volatile("cp.async.wait_group 1;");
        } else {
            asm volatile("cp.async.wait_group 0;");
        }
        __syncthreads();

        const uint32_t stb = sbase + (uint32_t)(((c % STAGES) * 2) * GTILE_E * 2);

#pragma unroll
        for (int ks = 0; ks < 64; ks += 16) {
            uint32_t Af[4][4];
#pragma unroll
            for (int mi = 0; mi < 4; mi++) {
                int row = warp_m * 64 + mi * 16 + lr;
                uint32_t a0 = stb + (uint32_t)((0 * GTILE_E + row * GLD + ks + kofs) * 2);
                ldmatrix_x4(Af[mi][0], Af[mi][1], Af[mi][2], Af[mi][3], a0);
            }
            uint32_t Bf[4][2];
#pragma unroll
            for (int bi = 0; bi < 2; bi++) {
                int row = warp_n * 32 + bi * 16 + lr;
                uint32_t b0 = stb + (uint32_t)((1 * GTILE_E + row * GLD + ks + kofs) * 2);
                uint32_t r0, r1, r2, r3;
                ldmatrix_x4(r0, r1, r2, r3, b0);
                Bf[bi * 2][0] = r0; Bf[bi * 2][1] = r2;
                Bf[bi * 2 + 1][0] = r1; Bf[bi * 2 + 1][1] = r3;
            }
#pragma unroll
            for (int mi = 0; mi < 4; mi++)
#pragma unroll
                for (int ni = 0; ni < 4; ni++)
                    mma_f16(acc[mi][ni], Af[mi][0], Af[mi][1], Af[mi][2], Af[mi][3],
                            Bf[ni][0], Bf[ni][1]);
        }
        __syncthreads();
    }

    const int g = lane >> 2, tig = lane & 3;
#pragma unroll
    for (int mi = 0; mi < 4; mi++) {
#pragma unroll
        for (int ni = 0; ni < 4; ni++) {
            int row = m0 + warp_m * 64 + mi * 16 + g;
            int col = n0 + warp_n * 32 + ni * 8 + tig * 2;
            float* d = acc[mi][ni];
            if (F32OUT) {
                *(float2*)&Cf[(size_t)row * N + col] = make_float2(d[0], d[1]);
                *(float2*)&Cf[(size_t)(row + 8) * N + col] = make_float2(d[2], d[3]);
            } else {
                __half2 h0 = __floats2half2_rn(d[0], d[1]);
                __half2 h1 = __floats2half2_rn(d[2], d[3]);
                *(uint32_t*)&Ch[(size_t)row * N + col] = *(uint32_t*)&h0;
                *(uint32_t*)&Ch[(size_t)(row + 8) * N + col] = *(uint32_t*)&h1;
            }
        }
    }
}

// ---------------------------------------------------------------------------
// Flash attention (R13 proven config): 1-term S, 1-term PV, static softmax,
// 64-key tiles, 3-stage KV pipeline.
// ---------------------------------------------------------------------------
#define FLD 72
#define FSTAGES 3
#define FLASH_SMEM ((128 * FLD + FSTAGES * 2 * 64 * FLD) * 2)   // 73728 B

__global__ __launch_bounds__(256, 2) void flash_mma(
    const __half* __restrict__ qkv, __half* __restrict__ oh)
{
    extern __shared__ __half smh[];
    __half* Qh = smh;
    __half* KV = smh + 128 * FLD;

    const int tid  = threadIdx.x;
    const int wid  = tid >> 5;
    const int lane = tid & 31;
    const int g    = lane >> 2;
    const int tq   = lane & 3;
    const int lr   = lane & 15;
    const int kofs = (lane & 16) ? 8 : 0;

    const int b  = blockIdx.y >> 3;
    const int h  = blockIdx.y & 7;
    const int q0 = blockIdx.x * 128;
    const size_t qrowg = (size_t)(b * SEQ + q0);

    {
#pragma unroll
        for (int q = 0; q < 4; q++) {
            int v = tid + q * 256;
            int row = v >> 3, seg = v & 7;
            cp_async16(smem_u32(Qh + row * FLD + seg * 8),
                       qkv + (qrowg + row) * QKVC + h * DHEAD + seg * 8);
        }
    }
    auto issue_kv = [&](int st, int ktile) {
        const size_t krow = (size_t)(b * SEQ + ktile * 64);
        __half* dst0 = KV + st * 2 * 64 * FLD;
#pragma unroll
        for (int t = 0; t < 2; t++) {
            const int colb = 512 + t * 512 + h * DHEAD;
#pragma unroll
            for (int q = 0; q < 2; q++) {
                int v = tid + q * 256;
                int row = v >> 3, seg = v & 7;
                cp_async16(smem_u32(dst0 + t * 64 * FLD + row * FLD + seg * 8),
                           qkv + (krow + row) * QKVC + colb + seg * 8);
            }
        }
        asm volatile("cp.async.commit_group;");
    };
    issue_kv(0, 0);   // group 0 = Q + KV0
    issue_kv(1, 1);   // group 1 = KV1

    float l_i[2] = {0.f, 0.f};
    float O[8][4];
#pragma unroll
    for (int j = 0; j < 8; j++)
#pragma unroll
        for (int r = 0; r < 4; r++) O[j][r] = 0.f;

    uint32_t qhf[4][4];

    const float CSC = 0.125f * 1.4426950408889634f;
    const int mi_pv = lane >> 3, ri_pv = lane & 7;
    const int keyb  = ((mi_pv & 1) << 3) + ri_pv;
    const int dimb  = (mi_pv >> 1) << 3;
    const int NIT = SEQ / 64;

    for (int c = 0; c < NIT; c++) {
        if (c + 2 < NIT) {
            issue_kv((c + 2) % FSTAGES, c + 2);
            asm volatile("cp.async.wait_group 2;");
        } else if (c + 1 < NIT) {
            asm volatile("cp.async.wait_group 1;");
        } else {
            asm volatile("cp.async.wait_group 0;");
        }
        __syncthreads();

        if (c == 0) {
#pragma unroll
            for (int kk = 0; kk < 4; kk++)
                ldmatrix_x4(qhf[kk][0], qhf[kk][1], qhf[kk][2], qhf[kk][3],
                    smem_u32(Qh + (wid * 16 + lr) * FLD + kk * 16 + kofs));
        }

        const __half* Kh = KV + (c % FSTAGES) * 2 * 64 * FLD;
        const __half* Vh = Kh + 64 * FLD;

        float S[8][4];
#pragma unroll
        for (int j = 0; j < 8; j++)
#pragma unroll
            for (int r = 0; r < 4; r++) S[j][r] = 0.f;

#pragma unroll
        for (int kk = 0; kk < 4; kk++) {
#pragma unroll
            for (int bi = 0; bi < 4; bi++) {
                uint32_t kh0, kh1, kh2, kh3;
                ldmatrix_x4(kh0, kh1, kh2, kh3,
                    smem_u32(Kh + (bi * 16 + lr) * FLD + kk * 16 + kofs));
                mma_f16(S[bi * 2],     qhf[kk][0], qhf[kk][1], qhf[kk][2], qhf[kk][3], kh0, kh2);
                mma_f16(S[bi * 2 + 1], qhf[kk][0], qhf[kk][1], qhf[kk][2], qhf[kk][3], kh1, kh3);
            }
        }

#pragma unroll
        for (int j = 0; j < 8; j++) {
            float p0 = ex2(S[j][0] * CSC);
            float p1 = ex2(S[j][1] * CSC);
            float p2 = ex2(S[j][2] * CSC);
            float p3 = ex2(S[j][3] * CSC);
            S[j][0] = p0; S[j][1] = p1; S[j][2] = p2; S[j][3] = p3;
            l_i[0] += p0 + p1;
            l_i[1] += p2 + p3;
        }

#pragma unroll
        for (int kk = 0; kk < 4; kk++) {
            uint32_t ph[4];
            ph[0] = pack_f16(S[2 * kk][0],     S[2 * kk][1]);
            ph[1] = pack_f16(S[2 * kk][2],     S[2 * kk][3]);
            ph[2] = pack_f16(S[2 * kk + 1][0], S[2 * kk + 1][1]);
            ph[3] = pack_f16(S[2 * kk + 1][2], S[2 * kk + 1][3]);

            const int key = kk * 16 + keyb;
#pragma unroll
            for (int jj = 0; jj < 4; jj++) {
                uint32_t t0, t1, t2, t3;
                ldmatrix_x4_trans(t0, t1, t2, t3,
                    smem_u32(Vh + key * FLD + jj * 16 + dimb));
                mma_f16(O[jj * 2],     ph[0], ph[1], ph[2], ph[3], t0, t1);
                mma_f16(O[jj * 2 + 1], ph[0], ph[1], ph[2], ph[3], t2, t3);
            }
        }
        __syncthreads();
    }

    l_i[0] += __shfl_xor_sync(0xffffffffu, l_i[0], 1);
    l_i[0] += __shfl_xor_sync(0xffffffffu, l_i[0], 2);
    l_i[1] += __shfl_xor_sync(0xffffffffu, l_i[1], 1);
    l_i[1] += __shfl_xor_sync(0xffffffffu, l_i[1], 2);
    const float inv0 = 1.f / l_i[0];
    const float inv1 = 1.f / l_i[1];
    const size_t row0 = qrowg + wid * 16 + g;
#pragma unroll
    for (int j = 0; j < 8; j++) {
        const int col = h * DHEAD + j * 8 + tq * 2;
        *(uint32_t*)&oh[row0 * DIM + col] =
            pack_f16(O[j][0] * inv0, O[j][1] * inv0);
        *(uint32_t*)&oh[(row0 + 8) * DIM + col] =
            pack_f16(O[j][2] * inv1, O[j][3] * inv1);
    }
}

// ---------------------------------------------------------------------------
extern "C" void kernel_launch(void* const* d_in, const int* in_sizes, int n_in,
                              void* d_out, int out_size)
{
    const float* x    = (const float*)d_in[0];
    const float* Wqkv = (const float*)d_in[1];
    const float* Wout = (const float*)d_in[2];
    float* out = (float*)d_out;

    __half *xh, *wh, *uh, *qkv, *ah;
    cudaGetSymbolAddress((void**)&xh,  g_xh);
    cudaGetSymbolAddress((void**)&wh,  g_wh);
    cudaGetSymbolAddress((void**)&uh,  g_uh);
    cudaGetSymbolAddress((void**)&qkv, g_qkv);
    cudaGetSymbolAddress((void**)&ah,  g_ah);

    cudaFuncSetAttribute((const void*)gemm_f16_1t<false, 3>,
                         cudaFuncAttributeMaxDynamicSharedMemorySize, GEMM_SMEM(3));
    cudaFuncSetAttribute((const void*)gemm_f16_1t<true, 2>,
                         cudaFuncAttributeMaxDynamicSharedMemorySize, GEMM_SMEM(2));
    cudaFuncSetAttribute(flash_mma,
                         cudaFuncAttributeMaxDynamicSharedMemorySize, FLASH_SMEM);

    // 0) all fp32 -> fp16 conversions in one launch
    conv_all<<<(N4_TOT + 255) / 256, 256>>>(
        (const float4*)x, xh, (const float4*)Wqkv, wh, (const float4*)Wout, uh);

    // 1) QKV projection (1-term fp16, BK=64, 3-stage) -> fp16 qkv
    gemm_f16_1t<false, 3><<<dim3(QKVC / 128, MTOT / 128), 256, GEMM_SMEM(3)>>>(
        xh, wh, qkv, nullptr, MTOT, QKVC, DIM);

    // 2) flash attention (R13 config: 64-key tiles, 3-stage KV) -> fp16
    flash_mma<<<dim3(SEQ / 128, BATCH * HEADS), 256, FLASH_SMEM>>>(qkv, ah);

    // 3) out projection (1-term fp16, BK=64, 2-stage) -> fp32
    gemm_f16_1t<true, 2><<<dim3(DIM / 128, MTOT / 128), 256, GEMM_SMEM(2)>>>(
        ah, uh, nullptr, out, MTOT, DIM, DIM);
}